// round 8
// baseline (speedup 1.0000x reference)
#include <cuda_runtime.h>
#include <cuda_fp16.h>
#include <math.h>
#include <stdint.h>

#define EPS 1e-5f
#define MAX_NORM 0.95f
#define D 128
#define MAXN 50000
#define MAXE 800000

// ---------------- scratch (static device globals) ---------------------------
__device__ float  g_v[MAXN * D];     // tangent vectors (GEMM input)
__device__ __half g_t16[MAXN * D];   // fp16 message tangents (gather source)
__device__ float  g_h[MAXN * D];     // inter-layer tangent state (fp32)
__device__ int    g_deg[MAXN];
__device__ int    g_off[MAXN + 1];
__device__ int    g_cur[MAXN];
__device__ int    g_csrc[MAXE];

// ---------------- scalar chains ---------------------------------------------
__device__ __forceinline__ float s_log0(float n) {
    float nm  = fmaxf(n, EPS);
    float arg = fminf(nm, 1.0f - EPS);
    return atanhf(arg) / nm;
}
__device__ __forceinline__ float chain_epl(float n) {
    float nm = fmaxf(n, EPS);
    float a  = tanhf(nm) / nm;
    float na = n * a;
    float b  = (na > MAX_NORM) ? MAX_NORM / fmaxf(na, EPS) : 1.0f;
    float nb = na * b;
    float nbm = fmaxf(nb, EPS);
    float arg = fminf(nbm, 1.0f - EPS);
    float c  = atanhf(arg) / nbm;
    return a * b * c;
}
__device__ __forceinline__ float chain_ep(float n) {
    float nm = fmaxf(n, EPS);
    float a  = tanhf(nm) / nm;
    float na = n * a;
    float b  = (na > MAX_NORM) ? MAX_NORM / fmaxf(na, EPS) : 1.0f;
    return a * b;
}

// ---------------- fp16 mma helper -------------------------------------------
__device__ __forceinline__ void mma_f16(float* d, uint32_t a0, uint32_t a1,
                                        uint32_t a2, uint32_t a3,
                                        uint32_t b0, uint32_t b1) {
    asm volatile(
        "mma.sync.aligned.m16n8k16.row.col.f32.f16.f16.f32 "
        "{%0,%1,%2,%3}, {%4,%5,%6,%7}, {%8,%9}, {%0,%1,%2,%3};\n"
        : "+f"(d[0]), "+f"(d[1]), "+f"(d[2]), "+f"(d[3])
        : "r"(a0), "r"(a1), "r"(a2), "r"(a3), "r"(b0), "r"(b1));
}
// split float pair into fp16 hi + fp16 residual lo (packed half2 words)
__device__ __forceinline__ void split2(float x, float y, uint32_t& hi, uint32_t& lo) {
    __half2 h = __floats2half2_rn(x, y);
    float2 hf = __half22float2(h);
    __half2 l = __floats2half2_rn(x - hf.x, y - hf.y);
    hi = *reinterpret_cast<uint32_t*>(&h);
    lo = *reinterpret_cast<uint32_t*>(&l);
}

// ---------------- CSR construction ------------------------------------------
__global__ void zero_int_kernel(int* __restrict__ p, int n) {
    int i = blockIdx.x * blockDim.x + threadIdx.x;
    if (i < n) p[i] = 0;
}
__global__ void hist_kernel(const int* __restrict__ dst, int E) {
    int e = blockIdx.x * blockDim.x + threadIdx.x;
    if (e < E) atomicAdd(&g_deg[dst[e]], 1);
}
__global__ void scan_kernel(int N) {
    int lane = threadIdx.x & 31, wid = threadIdx.x >> 5;
    __shared__ int wsum[32];
    __shared__ int running;
    if (threadIdx.x == 0) running = 0;
    __syncthreads();
    for (int base = 0; base < N; base += 1024) {
        int i = base + (int)threadIdx.x;
        int v = (i < N) ? g_deg[i] : 0;
        int x = v;
#pragma unroll
        for (int o = 1; o < 32; o <<= 1) {
            int y = __shfl_up_sync(0xffffffffu, x, o);
            if (lane >= o) x += y;
        }
        if (lane == 31) wsum[wid] = x;
        __syncthreads();
        if (wid == 0) {
            int s = wsum[lane];
#pragma unroll
            for (int o = 1; o < 32; o <<= 1) {
                int y = __shfl_up_sync(0xffffffffu, s, o);
                if (lane >= o) s += y;
            }
            wsum[lane] = s;
        }
        __syncthreads();
        int warp_prefix = (wid == 0) ? 0 : wsum[wid - 1];
        int excl = running + warp_prefix + (x - v);
        if (i < N) { g_off[i] = excl; g_cur[i] = excl; }
        int tile_total = wsum[31];
        __syncthreads();
        if (threadIdx.x == 0) running += tile_total;
        __syncthreads();
    }
    if (threadIdx.x == 0) g_off[N] = running;
}
__global__ void fill_kernel(const int* __restrict__ src, const int* __restrict__ dst, int E) {
    int e = blockIdx.x * blockDim.x + threadIdx.x;
    if (e < E) {
        int p = atomicAdd(&g_cur[dst[e]], 1);
        g_csrc[p] = src[e];
    }
}

// ---------------- prep: v = log0(x) -----------------------------------------
__global__ void prep_log0_kernel(const float* __restrict__ in, float* __restrict__ out, int N) {
    int w    = (blockIdx.x * blockDim.x + threadIdx.x) >> 5;
    int lane = threadIdx.x & 31;
    if (w >= N) return;
    float4 v = *reinterpret_cast<const float4*>(&in[(size_t)w * D + lane * 4]);
    float p = v.x * v.x + v.y * v.y + v.z * v.z + v.w * v.w;
#pragma unroll
    for (int off = 16; off; off >>= 1) p += __shfl_xor_sync(0xffffffffu, p, off);
    float s = s_log0(sqrtf(p));
    v.x *= s; v.y *= s; v.z *= s; v.w *= s;
    *reinterpret_cast<float4*>(&out[(size_t)w * D + lane * 4]) = v;
}

// ---------------- fused gather(fp16) + mean + chain_epl ---------------------
__global__ void agg_kernel(float* __restrict__ out, int N) {
    int w    = (blockIdx.x * blockDim.x + threadIdx.x) >> 5;
    int lane = threadIdx.x & 31;
    if (w >= N) return;
    int beg = g_off[w], end = g_off[w + 1];
    float ax = 0.f, ay = 0.f, az = 0.f, aw = 0.f;
    int e = beg;
    int col = lane * 4;
#pragma unroll 1
    for (; e + 4 <= end; e += 4) {
        int s0 = g_csrc[e], s1 = g_csrc[e + 1], s2 = g_csrc[e + 2], s3 = g_csrc[e + 3];
        uint2 u0 = *reinterpret_cast<const uint2*>(&g_t16[(size_t)s0 * D + col]);
        uint2 u1 = *reinterpret_cast<const uint2*>(&g_t16[(size_t)s1 * D + col]);
        uint2 u2 = *reinterpret_cast<const uint2*>(&g_t16[(size_t)s2 * D + col]);
        uint2 u3 = *reinterpret_cast<const uint2*>(&g_t16[(size_t)s3 * D + col]);
        float2 a, b;
        a = __half22float2(*(__half2*)&u0.x); b = __half22float2(*(__half2*)&u0.y);
        ax += a.x; ay += a.y; az += b.x; aw += b.y;
        a = __half22float2(*(__half2*)&u1.x); b = __half22float2(*(__half2*)&u1.y);
        ax += a.x; ay += a.y; az += b.x; aw += b.y;
        a = __half22float2(*(__half2*)&u2.x); b = __half22float2(*(__half2*)&u2.y);
        ax += a.x; ay += a.y; az += b.x; aw += b.y;
        a = __half22float2(*(__half2*)&u3.x); b = __half22float2(*(__half2*)&u3.y);
        ax += a.x; ay += a.y; az += b.x; aw += b.y;
    }
    for (; e < end; e++) {
        int s0 = g_csrc[e];
        uint2 u0 = *reinterpret_cast<const uint2*>(&g_t16[(size_t)s0 * D + col]);
        float2 a = __half22float2(*(__half2*)&u0.x);
        float2 b = __half22float2(*(__half2*)&u0.y);
        ax += a.x; ay += a.y; az += b.x; aw += b.y;
    }
    float inv = 1.0f / fmaxf((float)(end - beg), 1.0f);
    ax *= inv; ay *= inv; az *= inv; aw *= inv;
    float p = ax * ax + ay * ay + az * az + aw * aw;
#pragma unroll
    for (int off = 16; off; off >>= 1) p += __shfl_xor_sync(0xffffffffu, p, off);
    float s = chain_epl(sqrtf(p));
    float4 o = make_float4(ax * s, ay * s, az * s, aw * s);
    *reinterpret_cast<float4*>(&out[(size_t)w * D + col]) = o;
}

// ---------------- 3x fp16-split tensor-core GEMM + hyperbolic epilogue ------
// CTA: 64x128 output tile, K=128 resident, ~103 KB smem -> 2 CTAs/SM.
// 8 warps, warp tile 16x64. A,W pre-split to fp16 hi/lo at load.
// mode 0: chain_epl, fp16 store (message tangents)
// mode 1: chain_ep,  fp32 store (final output)
// mode 2: chain_epl, fp32 store (inter-layer tangent)
#define STR 68   // half2-word row stride: 68 mod 32 == 4 -> banks 4g+c, conflict-free
#define MT 64    // CTA rows

__global__ __launch_bounds__(256, 2) void gemm_hyp_tc_kernel(
    const float* __restrict__ V, const float* __restrict__ W,
    const float* __restrict__ bias, float* __restrict__ out,
    __half* __restrict__ out16, int N, int mode)
{
    extern __shared__ uint32_t smem_u[];
    uint32_t* Ahi = smem_u;                   // [MT][STR] half2 words
    uint32_t* Alo = Ahi + MT * STR;
    uint32_t* Whi = Alo + MT * STR;           // [128][STR]
    uint32_t* Wlo = Whi + 128 * STR;
    float* bias_s = (float*)(Wlo + 128 * STR);  // [128]
    float* red    = bias_s + 128;               // [MT][2]
    float* scl    = red + MT * 2;               // [MT]

    int tid  = threadIdx.x;
    int lane = tid & 31;
    int warp = tid >> 5;
    int rbase = (warp >> 1) * 16;   // 4 row groups of 16
    int cbase = (warp & 1) * 64;    // 2 col groups of 64
    int m0 = blockIdx.x * MT;

    if (tid < 128) bias_s[tid] = bias[tid];

    // ---- load A tile (64 rows x 32 float4-slots = 2048 slots) ----
#pragma unroll
    for (int i = 0; i < 8; i++) {
        int idx = tid + i * 256;            // 0..2047
        int row = idx >> 5;                 // 0..63
        int c4  = (idx & 31) * 4;
        int wofs = row * STR + (c4 >> 1);
        float4 av = make_float4(0.f, 0.f, 0.f, 0.f);
        int gm = m0 + row;
        if (gm < N) av = *reinterpret_cast<const float4*>(&V[(size_t)gm * D + c4]);
        uint32_t h0, l0, h1, l1;
        split2(av.x, av.y, h0, l0);
        split2(av.z, av.w, h1, l1);
        Ahi[wofs] = h0; Ahi[wofs + 1] = h1;
        Alo[wofs] = l0; Alo[wofs + 1] = l1;
    }
    // ---- load W tile (128 rows x 32 slots = 4096 slots) ----
#pragma unroll
    for (int i = 0; i < 16; i++) {
        int idx = tid + i * 256;            // 0..4095
        int row = idx >> 5;                 // 0..127
        int c4  = (idx & 31) * 4;
        int wofs = row * STR + (c4 >> 1);
        float4 wv = *reinterpret_cast<const float4*>(&W[(size_t)row * D + c4]);
        uint32_t h0, l0, h1, l1;
        split2(wv.x, wv.y, h0, l0);
        split2(wv.z, wv.w, h1, l1);
        Whi[wofs] = h0; Whi[wofs + 1] = h1;
        Wlo[wofs] = l0; Wlo[wofs + 1] = l1;
    }
    __syncthreads();

    float acc[8][4];
#pragma unroll
    for (int ct = 0; ct < 8; ct++)
#pragma unroll
        for (int q = 0; q < 4; q++) acc[ct][q] = 0.0f;

    int c = lane & 3;
    int g = lane >> 2;

#pragma unroll
    for (int ks = 0; ks < 8; ks++) {
        int k0 = ks * 8;                    // word offset of this k16 step
        int b0 = (rbase + g) * STR + k0 + c;
        int b1 = (rbase + 8 + g) * STR + k0 + c;
        uint32_t ah0 = Ahi[b0],     ah1 = Ahi[b1];
        uint32_t ah2 = Ahi[b0 + 4], ah3 = Ahi[b1 + 4];
        uint32_t al0 = Alo[b0],     al1 = Alo[b1];
        uint32_t al2 = Alo[b0 + 4], al3 = Alo[b1 + 4];
#pragma unroll
        for (int ct = 0; ct < 8; ct++) {
            int col = cbase + ct * 8 + g;
            int wb = col * STR + k0 + c;
            uint32_t bh0 = Whi[wb], bh1 = Whi[wb + 4];
            uint32_t bl0 = Wlo[wb], bl1 = Wlo[wb + 4];
            mma_f16(acc[ct], ah0, ah1, ah2, ah3, bh0, bh1);
            mma_f16(acc[ct], ah0, ah1, ah2, ah3, bl0, bl1);
            mma_f16(acc[ct], al0, al1, al2, al3, bh0, bh1);
        }
    }

    // ---- epilogue: bias add + per-row sumsq ----
    float prow0 = 0.f, prow1 = 0.f;
#pragma unroll
    for (int ct = 0; ct < 8; ct++) {
        int colb = cbase + ct * 8 + 2 * c;
        float u0 = acc[ct][0] + bias_s[colb];
        float u1 = acc[ct][1] + bias_s[colb + 1];
        float u2 = acc[ct][2] + bias_s[colb];
        float u3 = acc[ct][3] + bias_s[colb + 1];
        acc[ct][0] = u0; acc[ct][1] = u1;
        acc[ct][2] = u2; acc[ct][3] = u3;
        prow0 += u0 * u0 + u1 * u1;
        prow1 += u2 * u2 + u3 * u3;
    }
#pragma unroll
    for (int o = 1; o < 4; o <<= 1) {
        prow0 += __shfl_xor_sync(0xffffffffu, prow0, o);
        prow1 += __shfl_xor_sync(0xffffffffu, prow1, o);
    }
    int cg = warp & 1;
    if (c == 0) {
        red[(rbase + g) * 2 + cg]     = prow0;
        red[(rbase + 8 + g) * 2 + cg] = prow1;
    }
    __syncthreads();
    if (tid < MT) {
        float n = sqrtf(red[tid * 2] + red[tid * 2 + 1]);
        scl[tid] = (mode == 1) ? chain_ep(n) : chain_epl(n);
    }
    __syncthreads();

    // ---- scaled store ----
    {
        int r0 = rbase + g;
        float s0 = scl[r0];
        float s1 = scl[r0 + 8];
        int gm0 = m0 + r0;
        int gm1 = gm0 + 8;
#pragma unroll
        for (int ct = 0; ct < 8; ct++) {
            int colb = cbase + ct * 8 + 2 * c;
            if (mode == 0) {
                if (gm0 < N) {
                    __half2 hv = __floats2half2_rn(acc[ct][0] * s0, acc[ct][1] * s0);
                    *reinterpret_cast<__half2*>(&out16[(size_t)gm0 * D + colb]) = hv;
                }
                if (gm1 < N) {
                    __half2 hv = __floats2half2_rn(acc[ct][2] * s1, acc[ct][3] * s1);
                    *reinterpret_cast<__half2*>(&out16[(size_t)gm1 * D + colb]) = hv;
                }
            } else {
                if (gm0 < N) {
                    float2 o = make_float2(acc[ct][0] * s0, acc[ct][1] * s0);
                    *reinterpret_cast<float2*>(&out[(size_t)gm0 * D + colb]) = o;
                }
                if (gm1 < N) {
                    float2 o = make_float2(acc[ct][2] * s1, acc[ct][3] * s1);
                    *reinterpret_cast<float2*>(&out[(size_t)gm1 * D + colb]) = o;
                }
            }
        }
    }
}

// ---------------- host ------------------------------------------------------
extern "C" void kernel_launch(void* const* d_in, const int* in_sizes, int n_in,
                              void* d_out, int out_size)
{
    const float* x     = (const float*)d_in[0];
    const int*   ei    = (const int*)d_in[1];
    const float* msg_W = (const float*)d_in[2];
    const float* msg_b = (const float*)d_in[3];
    const float* upd_W = (const float*)d_in[4];
    const float* upd_b = (const float*)d_in[5];
    float* outp = (float*)d_out;

    int N = in_sizes[0] / D;
    int E = in_sizes[1] / 2;
    int L = in_sizes[3] / D;
    if (N > MAXN || E > MAXE) return;

    const int* src = ei;
    const int* dst = ei + E;

    float *p_v, *p_h;
    __half* p_t16;
    int *p_deg;
    cudaGetSymbolAddress((void**)&p_v,   g_v);
    cudaGetSymbolAddress((void**)&p_t16, g_t16);
    cudaGetSymbolAddress((void**)&p_h,   g_h);
    cudaGetSymbolAddress((void**)&p_deg, g_deg);

    const int SMEM = (2 * MT * STR + 2 * 128 * STR + 128 + MT * 2 + MT) * (int)sizeof(uint32_t);
    static bool init_done = false;
    static cudaStream_t s1;
    static cudaEvent_t ev_fork, ev_join;
    if (!init_done) {
        cudaFuncSetAttribute(gemm_hyp_tc_kernel,
                             cudaFuncAttributeMaxDynamicSharedMemorySize, SMEM);
        cudaStreamCreateWithFlags(&s1, cudaStreamNonBlocking);
        cudaEventCreateWithFlags(&ev_fork, cudaEventDisableTiming);
        cudaEventCreateWithFlags(&ev_join, cudaEventDisableTiming);
        init_done = true;
    }

    cudaStream_t s0 = 0;

    // ---- fork: CSR build on side stream ----
    cudaEventRecord(ev_fork, s0);
    cudaStreamWaitEvent(s1, ev_fork, 0);
    zero_int_kernel<<<(N + 255) / 256, 256, 0, s1>>>(p_deg, N);
    hist_kernel<<<(E + 255) / 256, 256, 0, s1>>>(dst, E);
    scan_kernel<<<1, 1024, 0, s1>>>(N);
    fill_kernel<<<(E + 255) / 256, 256, 0, s1>>>(src, dst, E);
    cudaEventRecord(ev_join, s1);

    int gemm_blocks  = (N + MT - 1) / MT;
    int warp_blocksN = (N * 32 + 255) / 256;

    prep_log0_kernel<<<warp_blocksN, 256>>>(x, p_v, N);

    bool joined = false;
    const float* v_in = p_v;
    for (int l = 0; l < L; l++) {
        gemm_hyp_tc_kernel<<<gemm_blocks, 256, SMEM>>>(v_in, msg_W + (size_t)l * D * D,
                                                       msg_b + (size_t)l * D,
                                                       nullptr, p_t16, N, 0);
        if (!joined) { cudaStreamWaitEvent(s0, ev_join, 0); joined = true; }
        agg_kernel<<<warp_blocksN, 256>>>(p_v, N);
        if (l == L - 1) {
            gemm_hyp_tc_kernel<<<gemm_blocks, 256, SMEM>>>(p_v, upd_W + (size_t)l * D * D,
                                                           upd_b + (size_t)l * D,
                                                           outp, nullptr, N, 1);
        } else {
            gemm_hyp_tc_kernel<<<gemm_blocks, 256, SMEM>>>(p_v, upd_W + (size_t)l * D * D,
                                                           upd_b + (size_t)l * D,
                                                           p_h, nullptr, N, 2);
            v_in = p_h;
        }
    }
}